// round 1
// baseline (speedup 1.0000x reference)
#include <cuda_runtime.h>
#include <math.h>

// Problem constants
#define NB   16
#define NS   1024
#define ND   512
#define NT   3
#define NBT  48   // NB*NT

// Scratch (static __device__ arrays: allowed; no runtime allocation)
__device__ float g_Q [(size_t)NBT * NS * ND];   // Q; later reused as "attended"
__device__ float g_K [(size_t)NBT * NS * ND];
__device__ float g_V [(size_t)NBT * NS * ND];
__device__ float g_Sc[(size_t)NBT * NS * NS];   // scores / probs

// ---------------------------------------------------------------------------
// Tiled SGEMM body: C[128 x 128] tile, BK=16, 256 threads, 8x8 per thread.
// BLAY=0: B is [N x K] row-major, K contiguous (i.e. C = A * B^T)
// BLAY=1: B is [K x N] row-major, N contiguous (i.e. C = A * B)
// ---------------------------------------------------------------------------
constexpr int BM = 128, BN = 128, BK = 16;

template<int BLAY, bool BIAS, bool SCALE>
__device__ __forceinline__ void gemm_body(
    const float* __restrict__ A, int lda,
    const float* __restrict__ Bm, int ldb,
    const float* __restrict__ bias, float alpha,
    float* __restrict__ C, int ldc, int K, int n0)
{
    __shared__ float As[BK][BM];
    __shared__ float Bs[BK][BN];

    const int tid  = threadIdx.x;
    const int tx   = tid & 15;      // row-group selector (16)
    const int ty   = tid >> 4;      // col-group selector (16)
    const int arow = tid >> 2;      // 0..63 (load row)
    const int akq  = tid & 3;       // 0..3  (which float4 along k)
    const int bkr  = tid >> 5;      // 0..7  (NN load k-row)
    const int bnq  = tid & 31;      // 0..31 (NN load col quad)

    float acc[8][8];
#pragma unroll
    for (int i = 0; i < 8; i++)
#pragma unroll
        for (int j = 0; j < 8; j++) acc[i][j] = 0.f;

    float4 ra[2], rb[2];
    // prefetch chunk 0
#pragma unroll
    for (int i = 0; i < 2; i++)
        ra[i] = *(const float4*)(A + (size_t)(arow + 64*i) * lda + akq*4);
    if (BLAY == 0) {
#pragma unroll
        for (int i = 0; i < 2; i++)
            rb[i] = *(const float4*)(Bm + (size_t)(n0 + arow + 64*i) * ldb + akq*4);
    } else {
#pragma unroll
        for (int i = 0; i < 2; i++)
            rb[i] = *(const float4*)(Bm + (size_t)(bkr + 8*i) * ldb + n0 + bnq*4);
    }

    for (int k0 = 0; k0 < K; k0 += BK) {
        // regs -> smem
#pragma unroll
        for (int i = 0; i < 2; i++) {
            int r = arow + 64*i;
            As[akq*4+0][r] = ra[i].x; As[akq*4+1][r] = ra[i].y;
            As[akq*4+2][r] = ra[i].z; As[akq*4+3][r] = ra[i].w;
        }
        if (BLAY == 0) {
#pragma unroll
            for (int i = 0; i < 2; i++) {
                int r = arow + 64*i;
                Bs[akq*4+0][r] = rb[i].x; Bs[akq*4+1][r] = rb[i].y;
                Bs[akq*4+2][r] = rb[i].z; Bs[akq*4+3][r] = rb[i].w;
            }
        } else {
#pragma unroll
            for (int i = 0; i < 2; i++)
                *(float4*)&Bs[bkr + 8*i][bnq*4] = rb[i];
        }
        __syncthreads();

        // prefetch next chunk while computing this one
        int kn = k0 + BK;
        if (kn < K) {
#pragma unroll
            for (int i = 0; i < 2; i++)
                ra[i] = *(const float4*)(A + (size_t)(arow + 64*i) * lda + kn + akq*4);
            if (BLAY == 0) {
#pragma unroll
                for (int i = 0; i < 2; i++)
                    rb[i] = *(const float4*)(Bm + (size_t)(n0 + arow + 64*i) * ldb + kn + akq*4);
            } else {
#pragma unroll
                for (int i = 0; i < 2; i++)
                    rb[i] = *(const float4*)(Bm + (size_t)(kn + bkr + 8*i) * ldb + n0 + bnq*4);
            }
        }

#pragma unroll
        for (int kk = 0; kk < BK; kk++) {
            float4 a0 = *(const float4*)&As[kk][tx*4];
            float4 a1 = *(const float4*)&As[kk][64 + tx*4];
            float4 b0 = *(const float4*)&Bs[kk][ty*4];
            float4 b1 = *(const float4*)&Bs[kk][64 + ty*4];
            float av[8] = {a0.x,a0.y,a0.z,a0.w,a1.x,a1.y,a1.z,a1.w};
            float bw[8] = {b0.x,b0.y,b0.z,b0.w,b1.x,b1.y,b1.z,b1.w};
#pragma unroll
            for (int i = 0; i < 8; i++)
#pragma unroll
                for (int j = 0; j < 8; j++)
                    acc[i][j] = fmaf(av[i], bw[j], acc[i][j]);
        }
        __syncthreads();
    }

    // epilogue
    float bb[8];
    if (BIAS) {
#pragma unroll
        for (int j = 0; j < 8; j++) {
            int c = n0 + ((j < 4) ? ty*4 + j : 64 + ty*4 + (j - 4));
            bb[j] = bias[c];
        }
    }
#pragma unroll
    for (int i = 0; i < 8; i++) {
        int r = (i < 4) ? tx*4 + i : 64 + tx*4 + (i - 4);
        float vs[8];
#pragma unroll
        for (int j = 0; j < 8; j++) {
            float v = acc[i][j];
            if (SCALE) v *= alpha;
            if (BIAS)  v += bb[j];
            vs[j] = v;
        }
        *(float4*)(C + (size_t)r * ldc + n0 + ty*4)      = make_float4(vs[0],vs[1],vs[2],vs[3]);
        *(float4*)(C + (size_t)r * ldc + n0 + 64 + ty*4) = make_float4(vs[4],vs[5],vs[6],vs[7]);
    }
}

// ---------------------------------------------------------------------------
// Kernel 1: QKV projections.  grid = (ND/128=4, 384, 3[q,k,v]), block 256
// ---------------------------------------------------------------------------
__global__ __launch_bounds__(256)
void k_qkv(const float* __restrict__ f4h, const float* __restrict__ f1d,
           const float* __restrict__ f1w,
           const float* __restrict__ Wq, const float* __restrict__ bq,
           const float* __restrict__ Wk, const float* __restrict__ bk,
           const float* __restrict__ Wv, const float* __restrict__ bv)
{
    const int mt = blockIdx.y;            // 0..383 (49152 rows / 128)
    const int bt = mt >> 3;               // 0..47
    const int b  = bt / NT, t = bt % NT;

    const float* f = (t == 0) ? f4h : (t == 1) ? f1d : f1w;
    const float* A = f + ((size_t)b * NS + (size_t)(mt & 7) * BM) * ND;

    const float* W; const float* bias; float* Cbuf;
    if (blockIdx.z == 0)      { W = Wq; bias = bq; Cbuf = g_Q; }
    else if (blockIdx.z == 1) { W = Wk; bias = bk; Cbuf = g_K; }
    else                      { W = Wv; bias = bv; Cbuf = g_V; }

    float* C = Cbuf + (size_t)mt * BM * ND;
    gemm_body<0, true, false>(A, ND, W, ND, bias, 1.f, C, ND, ND, blockIdx.x * BN);
}

// ---------------------------------------------------------------------------
// Kernel 2: scores = scale * Q K^T.  grid = (NS/128=8, 384), block 256
// ---------------------------------------------------------------------------
__global__ __launch_bounds__(256)
void k_scores()
{
    const int mt = blockIdx.y;
    const int bt = mt >> 3;
    const float* A = g_Q + (size_t)mt * BM * ND;
    const float* Bp = g_K + (size_t)bt * NS * ND;
    float* C = g_Sc + (size_t)mt * BM * NS;
    gemm_body<0, false, true>(A, ND, Bp, ND, nullptr, 0.044194173824159216f,
                              C, NS, ND, blockIdx.x * BN);
}

// ---------------------------------------------------------------------------
// Kernel 3: row softmax over 49152 rows of 1024. warp per row, 8 rows/block
// ---------------------------------------------------------------------------
__global__ __launch_bounds__(256)
void k_softmax()
{
    const int row  = blockIdx.x * 8 + (threadIdx.x >> 5);
    const int lane = threadIdx.x & 31;
    float4* p = (float4*)(g_Sc + (size_t)row * NS);

    float4 v[8];
    float m = -1e30f;
#pragma unroll
    for (int i = 0; i < 8; i++) {
        v[i] = p[lane + 32*i];
        m = fmaxf(m, fmaxf(fmaxf(v[i].x, v[i].y), fmaxf(v[i].z, v[i].w)));
    }
#pragma unroll
    for (int off = 16; off >= 1; off >>= 1)
        m = fmaxf(m, __shfl_xor_sync(0xffffffffu, m, off));

    float s = 0.f;
#pragma unroll
    for (int i = 0; i < 8; i++) {
        v[i].x = __expf(v[i].x - m); v[i].y = __expf(v[i].y - m);
        v[i].z = __expf(v[i].z - m); v[i].w = __expf(v[i].w - m);
        s += v[i].x + v[i].y + v[i].z + v[i].w;
    }
#pragma unroll
    for (int off = 16; off >= 1; off >>= 1)
        s += __shfl_xor_sync(0xffffffffu, s, off);

    const float inv = 1.0f / s;
#pragma unroll
    for (int i = 0; i < 8; i++) {
        v[i].x *= inv; v[i].y *= inv; v[i].z *= inv; v[i].w *= inv;
        p[lane + 32*i] = v[i];
    }
}

// ---------------------------------------------------------------------------
// Kernel 4: attended = P V  (NN GEMM, K=1024). grid = (ND/128=4, 384)
// Writes into g_Q (Q is dead after kernel 2).
// ---------------------------------------------------------------------------
__global__ __launch_bounds__(256)
void k_pv()
{
    const int mt = blockIdx.y;
    const int bt = mt >> 3;
    const float* A = g_Sc + (size_t)mt * BM * NS;      // probs, lda = 1024
    const float* Bp = g_V + (size_t)bt * NS * ND;      // V, ldb = 512 (NN)
    float* C = g_Q + (size_t)mt * BM * ND;
    gemm_body<1, false, false>(A, NS, Bp, ND, nullptr, 1.f, C, ND, NS, blockIdx.x * BN);
}

// ---------------------------------------------------------------------------
// Kernel 5: out[b,s,d] = sum_t softmax(tfw)[t] * attended[b*3+t, s, d]
// ---------------------------------------------------------------------------
__global__ __launch_bounds__(256)
void k_combine(const float* __restrict__ tfw, float* __restrict__ out)
{
    float w0 = tfw[0], w1 = tfw[1], w2 = tfw[2];
    float mx = fmaxf(w0, fmaxf(w1, w2));
    float e0 = __expf(w0 - mx), e1 = __expf(w1 - mx), e2 = __expf(w2 - mx);
    float inv = 1.0f / (e0 + e1 + e2);
    w0 = e0 * inv; w1 = e1 * inv; w2 = e2 * inv;

    const size_t per_b = (size_t)NS * ND / 4;          // 131072 float4 per (b,t)
    size_t idx = (size_t)blockIdx.x * blockDim.x + threadIdx.x;
    const size_t n4 = (size_t)NB * per_b;
    if (idx >= n4) return;
    size_t b = idx / per_b;
    size_t r = idx % per_b;

    const float4* A = (const float4*)g_Q;
    float4 x0 = A[(b*3 + 0) * per_b + r];
    float4 x1 = A[(b*3 + 1) * per_b + r];
    float4 x2 = A[(b*3 + 2) * per_b + r];
    float4 o;
    o.x = w0*x0.x + w1*x1.x + w2*x2.x;
    o.y = w0*x0.y + w1*x1.y + w2*x2.y;
    o.z = w0*x0.z + w1*x1.z + w2*x2.z;
    o.w = w0*x0.w + w1*x1.w + w2*x2.w;
    ((float4*)out)[idx] = o;
}

// ---------------------------------------------------------------------------
extern "C" void kernel_launch(void* const* d_in, const int* in_sizes, int n_in,
                              void* d_out, int out_size)
{
    (void)in_sizes; (void)n_in; (void)out_size;
    const float* f4h = (const float*)d_in[0];
    const float* f1d = (const float*)d_in[1];
    const float* f1w = (const float*)d_in[2];
    const float* Wq  = (const float*)d_in[3];
    const float* bq  = (const float*)d_in[4];
    const float* Wk  = (const float*)d_in[5];
    const float* bk  = (const float*)d_in[6];
    const float* Wv  = (const float*)d_in[7];
    const float* bv  = (const float*)d_in[8];
    const float* tfw = (const float*)d_in[9];
    float* out = (float*)d_out;

    dim3 blk(256);
    k_qkv    <<<dim3(ND/BN, (NBT*NS)/BM, 3), blk>>>(f4h, f1d, f1w, Wq, bq, Wk, bk, Wv, bv);
    k_scores <<<dim3(NS/BN, (NBT*NS)/BM),    blk>>>();
    k_softmax<<<(NBT*NS)/8,                  blk>>>();
    k_pv     <<<dim3(ND/BN, (NBT*NS)/BM),    blk>>>();
    k_combine<<<(NB*NS*ND/4 + 255)/256,      blk>>>(tfw, out);
}

// round 2
// speedup vs baseline: 2.3420x; 2.3420x over previous
#include <cuda_runtime.h>
#include <math.h>
#include <stdint.h>

#define NB   16
#define NS   1024
#define ND   512
#define NT   3
#define NBT  48

__device__ float g_Q [(size_t)NBT * NS * ND];   // Q; reused as attended
__device__ float g_K [(size_t)NBT * NS * ND];
__device__ float g_V [(size_t)NBT * NS * ND];
__device__ float g_Sc[(size_t)NBT * NS * NS];   // scores / probs

// ---------------------------------------------------------------------------
// tf32 warp-MMA GEMM: C[128x128] per CTA, BK=16, 256 threads (8 warps, 2x4),
// warp tile 64x32, mma.m16n8k8, fp32 accumulate.
// BLAY=0: B is [N x K] row-major (K contig)  -> C = A * B^T
// BLAY=1: B is [K x N] row-major (N contig)  -> C = A * B
// ---------------------------------------------------------------------------
#define ASTR 20     // As row stride (16 + 4 pad) -> conflict-free frag loads
#define BSTR 132    // Bs row stride for BLAY=1 [k][n]

__device__ __forceinline__ uint32_t f2tf32(float x) {
    uint32_t r;
    asm("cvt.rna.tf32.f32 %0, %1;" : "=r"(r) : "f"(x));
    return r;
}

__device__ __forceinline__ void mma_tf32(float c[4], const uint32_t a[4], const uint32_t b[2]) {
    asm volatile(
        "mma.sync.aligned.m16n8k8.row.col.f32.tf32.tf32.f32 "
        "{%0,%1,%2,%3}, {%4,%5,%6,%7}, {%8,%9}, {%0,%1,%2,%3};"
        : "+f"(c[0]), "+f"(c[1]), "+f"(c[2]), "+f"(c[3])
        : "r"(a[0]), "r"(a[1]), "r"(a[2]), "r"(a[3]), "r"(b[0]), "r"(b[1]));
}

template<int BLAY, bool BIAS, bool SCALE>
__device__ __forceinline__ void gemm_tf32(
    const float* __restrict__ A, int lda,
    const float* __restrict__ Bm, int ldb,
    const float* __restrict__ bias, float alpha,
    float* __restrict__ C, int ldc, int K, int n0)
{
    __shared__ uint32_t As[2][128 * ASTR];
    __shared__ uint32_t Bs[2][BLAY ? 16 * BSTR : 128 * ASTR];

    const int tid  = threadIdx.x;
    const int lane = tid & 31;
    const int wid  = tid >> 5;
    const int g    = lane >> 2;     // 0..7
    const int tig  = lane & 3;      // 0..3
    const int wm   = (wid >> 2) * 64;
    const int wn   = (wid & 3) * 32;

    // staging indices
    const int ar = tid >> 2;        // 0..63
    const int aq = tid & 3;         // 0..3
    const int bk = tid >> 5;        // 0..7   (BLAY=1)
    const int bn = tid & 31;        // 0..31  (BLAY=1)

    float acc[4][4][4];
#pragma unroll
    for (int i = 0; i < 4; i++)
#pragma unroll
        for (int j = 0; j < 4; j++)
#pragma unroll
            for (int q = 0; q < 4; q++) acc[i][j][q] = 0.f;

    uint32_t ra[8], rb[8];

    auto ldA = [&](int k0) {
#pragma unroll
        for (int i = 0; i < 2; i++) {
            float4 v = *(const float4*)(A + (size_t)(ar + 64*i) * lda + k0 + aq*4);
            ra[4*i+0] = f2tf32(v.x); ra[4*i+1] = f2tf32(v.y);
            ra[4*i+2] = f2tf32(v.z); ra[4*i+3] = f2tf32(v.w);
        }
    };
    auto ldB = [&](int k0) {
        if (BLAY == 0) {
#pragma unroll
            for (int i = 0; i < 2; i++) {
                float4 v = *(const float4*)(Bm + (size_t)(n0 + ar + 64*i) * ldb + k0 + aq*4);
                rb[4*i+0] = f2tf32(v.x); rb[4*i+1] = f2tf32(v.y);
                rb[4*i+2] = f2tf32(v.z); rb[4*i+3] = f2tf32(v.w);
            }
        } else {
#pragma unroll
            for (int i = 0; i < 2; i++) {
                float4 v = *(const float4*)(Bm + (size_t)(k0 + bk + 8*i) * ldb + n0 + bn*4);
                rb[4*i+0] = f2tf32(v.x); rb[4*i+1] = f2tf32(v.y);
                rb[4*i+2] = f2tf32(v.z); rb[4*i+3] = f2tf32(v.w);
            }
        }
    };
    auto stA = [&](int buf) {
#pragma unroll
        for (int i = 0; i < 2; i++)
            *(uint4*)&As[buf][(ar + 64*i) * ASTR + aq*4] =
                make_uint4(ra[4*i], ra[4*i+1], ra[4*i+2], ra[4*i+3]);
    };
    auto stB = [&](int buf) {
        if (BLAY == 0) {
#pragma unroll
            for (int i = 0; i < 2; i++)
                *(uint4*)&Bs[buf][(ar + 64*i) * ASTR + aq*4] =
                    make_uint4(rb[4*i], rb[4*i+1], rb[4*i+2], rb[4*i+3]);
        } else {
#pragma unroll
            for (int i = 0; i < 2; i++)
                *(uint4*)&Bs[buf][(bk + 8*i) * BSTR + bn*4] =
                    make_uint4(rb[4*i], rb[4*i+1], rb[4*i+2], rb[4*i+3]);
        }
    };

    ldA(0); ldB(0);
    stA(0); stB(0);
    __syncthreads();

    const int niter = K / 16;
    for (int it = 0; it < niter; it++) {
        const int cb = it & 1, nb = cb ^ 1;
        if (it + 1 < niter) { ldA((it+1)*16); ldB((it+1)*16); }

#pragma unroll
        for (int kk = 0; kk < 16; kk += 8) {
            uint32_t af[4][4], bf[4][2];
#pragma unroll
            for (int mt = 0; mt < 4; mt++) {
                int row = wm + mt*16 + g;
                af[mt][0] = As[cb][row*ASTR + kk + tig];
                af[mt][1] = As[cb][(row+8)*ASTR + kk + tig];
                af[mt][2] = As[cb][row*ASTR + kk + tig + 4];
                af[mt][3] = As[cb][(row+8)*ASTR + kk + tig + 4];
            }
#pragma unroll
            for (int nt = 0; nt < 4; nt++) {
                int n = wn + nt*8 + g;
                if (BLAY == 0) {
                    bf[nt][0] = Bs[cb][n*ASTR + kk + tig];
                    bf[nt][1] = Bs[cb][n*ASTR + kk + tig + 4];
                } else {
                    bf[nt][0] = Bs[cb][(kk + tig)*BSTR + n];
                    bf[nt][1] = Bs[cb][(kk + tig + 4)*BSTR + n];
                }
            }
#pragma unroll
            for (int mt = 0; mt < 4; mt++)
#pragma unroll
                for (int nt = 0; nt < 4; nt++)
                    mma_tf32(acc[mt][nt], af[mt], bf[nt]);
        }

        if (it + 1 < niter) { stA(nb); stB(nb); }
        __syncthreads();
    }

    // epilogue: c0:(row,col) c1:(row,col+1) c2:(row+8,col) c3:(row+8,col+1)
#pragma unroll
    for (int nt = 0; nt < 4; nt++) {
        const int col = n0 + wn + nt*8 + tig*2;
        float b0 = 0.f, b1 = 0.f;
        if (BIAS) { b0 = bias[col]; b1 = bias[col+1]; }
#pragma unroll
        for (int mt = 0; mt < 4; mt++) {
            const int row = wm + mt*16 + g;
            float v0 = acc[mt][nt][0], v1 = acc[mt][nt][1];
            float v2 = acc[mt][nt][2], v3 = acc[mt][nt][3];
            if (SCALE) { v0 *= alpha; v1 *= alpha; v2 *= alpha; v3 *= alpha; }
            if (BIAS)  { v0 += b0; v1 += b1; v2 += b0; v3 += b1; }
            *(float2*)(C + (size_t)row * ldc + col)       = make_float2(v0, v1);
            *(float2*)(C + (size_t)(row+8) * ldc + col)   = make_float2(v2, v3);
        }
    }
}

// ---------------------------------------------------------------------------
__global__ __launch_bounds__(256)
void k_qkv(const float* __restrict__ f4h, const float* __restrict__ f1d,
           const float* __restrict__ f1w,
           const float* __restrict__ Wq, const float* __restrict__ bq,
           const float* __restrict__ Wk, const float* __restrict__ bk,
           const float* __restrict__ Wv, const float* __restrict__ bv)
{
    const int mt = blockIdx.y;
    const int bt = mt >> 3;
    const int b  = bt / NT, t = bt % NT;
    const float* f = (t == 0) ? f4h : (t == 1) ? f1d : f1w;
    const float* A = f + ((size_t)b * NS + (size_t)(mt & 7) * 128) * ND;

    const float* W; const float* bias; float* Cbuf;
    if (blockIdx.z == 0)      { W = Wq; bias = bq; Cbuf = g_Q; }
    else if (blockIdx.z == 1) { W = Wk; bias = bk; Cbuf = g_K; }
    else                      { W = Wv; bias = bv; Cbuf = g_V; }

    float* C = Cbuf + (size_t)mt * 128 * ND;
    gemm_tf32<0, true, false>(A, ND, W, ND, bias, 1.f, C, ND, ND, blockIdx.x * 128);
}

__global__ __launch_bounds__(256)
void k_scores()
{
    const int mt = blockIdx.y;
    const int bt = mt >> 3;
    const float* A  = g_Q + (size_t)mt * 128 * ND;
    const float* Bp = g_K + (size_t)bt * NS * ND;
    float* C = g_Sc + (size_t)mt * 128 * NS;
    gemm_tf32<0, false, true>(A, ND, Bp, ND, nullptr, 0.044194173824159216f,
                              C, NS, ND, blockIdx.x * 128);
}

__global__ __launch_bounds__(256)
void k_softmax()
{
    const int row  = blockIdx.x * 8 + (threadIdx.x >> 5);
    const int lane = threadIdx.x & 31;
    float4* p = (float4*)(g_Sc + (size_t)row * NS);

    float4 v[8];
    float m = -1e30f;
#pragma unroll
    for (int i = 0; i < 8; i++) {
        v[i] = p[lane + 32*i];
        m = fmaxf(m, fmaxf(fmaxf(v[i].x, v[i].y), fmaxf(v[i].z, v[i].w)));
    }
#pragma unroll
    for (int off = 16; off >= 1; off >>= 1)
        m = fmaxf(m, __shfl_xor_sync(0xffffffffu, m, off));

    float s = 0.f;
#pragma unroll
    for (int i = 0; i < 8; i++) {
        v[i].x = __expf(v[i].x - m); v[i].y = __expf(v[i].y - m);
        v[i].z = __expf(v[i].z - m); v[i].w = __expf(v[i].w - m);
        s += v[i].x + v[i].y + v[i].z + v[i].w;
    }
#pragma unroll
    for (int off = 16; off >= 1; off >>= 1)
        s += __shfl_xor_sync(0xffffffffu, s, off);

    const float inv = 1.0f / s;
#pragma unroll
    for (int i = 0; i < 8; i++) {
        v[i].x *= inv; v[i].y *= inv; v[i].z *= inv; v[i].w *= inv;
        p[lane + 32*i] = v[i];
    }
}

__global__ __launch_bounds__(256)
void k_pv()
{
    const int mt = blockIdx.y;
    const int bt = mt >> 3;
    const float* A  = g_Sc + (size_t)mt * 128 * NS;   // probs
    const float* Bp = g_V + (size_t)bt * NS * ND;     // V [K x N], N contig
    float* C = g_Q + (size_t)mt * 128 * ND;
    gemm_tf32<1, false, false>(A, NS, Bp, ND, nullptr, 1.f, C, ND, NS, blockIdx.x * 128);
}

__global__ __launch_bounds__(256)
void k_combine(const float* __restrict__ tfw, float* __restrict__ out)
{
    float w0 = tfw[0], w1 = tfw[1], w2 = tfw[2];
    float mx = fmaxf(w0, fmaxf(w1, w2));
    float e0 = __expf(w0 - mx), e1 = __expf(w1 - mx), e2 = __expf(w2 - mx);
    float inv = 1.0f / (e0 + e1 + e2);
    w0 = e0 * inv; w1 = e1 * inv; w2 = e2 * inv;

    const size_t per_b = (size_t)NS * ND / 4;
    size_t idx = (size_t)blockIdx.x * blockDim.x + threadIdx.x;
    const size_t n4 = (size_t)NB * per_b;
    if (idx >= n4) return;
    size_t b = idx / per_b;
    size_t r = idx % per_b;

    const float4* A = (const float4*)g_Q;
    float4 x0 = A[(b*3 + 0) * per_b + r];
    float4 x1 = A[(b*3 + 1) * per_b + r];
    float4 x2 = A[(b*3 + 2) * per_b + r];
    float4 o;
    o.x = w0*x0.x + w1*x1.x + w2*x2.x;
    o.y = w0*x0.y + w1*x1.y + w2*x2.y;
    o.z = w0*x0.z + w1*x1.z + w2*x2.z;
    o.w = w0*x0.w + w1*x1.w + w2*x2.w;
    ((float4*)out)[idx] = o;
}

// ---------------------------------------------------------------------------
extern "C" void kernel_launch(void* const* d_in, const int* in_sizes, int n_in,
                              void* d_out, int out_size)
{
    (void)in_sizes; (void)n_in; (void)out_size;
    const float* f4h = (const float*)d_in[0];
    const float* f1d = (const float*)d_in[1];
    const float* f1w = (const float*)d_in[2];
    const float* Wq  = (const float*)d_in[3];
    const float* bq  = (const float*)d_in[4];
    const float* Wk  = (const float*)d_in[5];
    const float* bk  = (const float*)d_in[6];
    const float* Wv  = (const float*)d_in[7];
    const float* bv  = (const float*)d_in[8];
    const float* tfw = (const float*)d_in[9];
    float* out = (float*)d_out;

    dim3 blk(256);
    k_qkv    <<<dim3(ND/128, (NBT*NS)/128, 3), blk>>>(f4h, f1d, f1w, Wq, bq, Wk, bk, Wv, bv);
    k_scores <<<dim3(NS/128, (NBT*NS)/128),    blk>>>();
    k_softmax<<<(NBT*NS)/8,                    blk>>>();
    k_pv     <<<dim3(ND/128, (NBT*NS)/128),    blk>>>();
    k_combine<<<(NB*NS*ND/4 + 255)/256,        blk>>>(tfw, out);
}

// round 6
// speedup vs baseline: 2.5169x; 1.0747x over previous
#include <cuda_runtime.h>
#include <math.h>
#include <stdint.h>

#define NB   16
#define NS   1024
#define ND   512
#define NT   3
#define NBT  48

__device__ float g_Q [(size_t)NBT * NS * ND];   // Q; reused as attended
__device__ float g_K [(size_t)NBT * NS * ND];
__device__ float g_V [(size_t)NBT * NS * ND];
__device__ float g_Sc[(size_t)NBT * NS * NS];   // scores / probs

// ---------------------------------------------------------------------------
// tf32 warp-MMA GEMM v2: CTA tile 128(M) x 256(N), BK=16, 256 threads,
// 8 warps in 2x4 grid, warp tile 64x64, mma.m16n8k8 tf32, fp32 accum.
// BLAY=0: B is [N x K] row-major (K contig)  -> C = A * B^T
// BLAY=1: B is [K x N] row-major (N contig)  -> C = A * B
// ---------------------------------------------------------------------------
#define ASTR 20     // As/Bs(K-major) row stride: banks 20g+tig cover 0..31
#define BSTR 264    // Bs(N-major) row stride: 264%32=8 -> tig*8+g conflict-free

// word offsets inside dynamic smem (macros: device-visible, no odr-use issues)
#define A_OFFW(buf) ((buf) * 2560)            // 128*20 per buffer
#define B_OFFW(buf) (5120 + (buf) * 5120)     // max(256*20, 16*264)=5120 per buffer
#define SMEM_WORDS  15360                     // 61440 bytes

constexpr int BM = 128, BN = 256, BK = 16;

__device__ __forceinline__ uint32_t f2tf32(float x) {
    uint32_t r; asm("cvt.rna.tf32.f32 %0, %1;" : "=r"(r) : "f"(x)); return r;
}
__device__ __forceinline__ void mma_tf32(float c[4], const uint32_t a[4], const uint32_t b[2]) {
    asm volatile(
        "mma.sync.aligned.m16n8k8.row.col.f32.tf32.tf32.f32 "
        "{%0,%1,%2,%3}, {%4,%5,%6,%7}, {%8,%9}, {%0,%1,%2,%3};"
        : "+f"(c[0]), "+f"(c[1]), "+f"(c[2]), "+f"(c[3])
        : "r"(a[0]), "r"(a[1]), "r"(a[2]), "r"(a[3]), "r"(b[0]), "r"(b[1]));
}

template<int BLAY, bool BIAS, bool SCALE>
__device__ __forceinline__ void gemm_tf32(
    const float* __restrict__ A, int lda,
    const float* __restrict__ Bm, int ldb,
    const float* __restrict__ bias, float alpha,
    float* __restrict__ C, int ldc, int K, int n0)
{
    extern __shared__ uint32_t sh[];

    const int tid  = threadIdx.x;
    const int lane = tid & 31;
    const int wid  = tid >> 5;
    const int g    = lane >> 2;      // 0..7
    const int tig  = lane & 3;       // 0..3
    const int wm   = (wid & 1) * 64; // 2 warp rows
    const int wn   = (wid >> 1) * 64;// 4 warp cols

    // staging indices
    const int sr = tid >> 2;         // 0..63
    const int sq = tid & 3;          // 0..3
    const int vk = tid >> 6;         // 0..3   (BLAY=1)
    const int vn = tid & 63;         // 0..63  (BLAY=1)

    float acc[4][8][4];
#pragma unroll
    for (int i = 0; i < 4; i++)
#pragma unroll
        for (int j = 0; j < 8; j++)
#pragma unroll
            for (int q = 0; q < 4; q++) acc[i][j][q] = 0.f;

    float4 ra[2], rb[4];

    auto ldA = [&](int k0) {
#pragma unroll
        for (int i = 0; i < 2; i++)
            ra[i] = *(const float4*)(A + (size_t)(sr + 64*i) * lda + k0 + sq*4);
    };
    auto ldB = [&](int k0) {
        if (BLAY == 0) {
#pragma unroll
            for (int i = 0; i < 4; i++)
                rb[i] = *(const float4*)(Bm + (size_t)(n0 + sr + 64*i) * ldb + k0 + sq*4);
        } else {
#pragma unroll
            for (int i = 0; i < 4; i++)
                rb[i] = *(const float4*)(Bm + (size_t)(k0 + vk + 4*i) * ldb + n0 + vn*4);
        }
    };
    auto stA = [&](int buf) {
#pragma unroll
        for (int i = 0; i < 2; i++)
            *(uint4*)&sh[A_OFFW(buf) + (sr + 64*i) * ASTR + sq*4] =
                make_uint4(f2tf32(ra[i].x), f2tf32(ra[i].y), f2tf32(ra[i].z), f2tf32(ra[i].w));
    };
    auto stB = [&](int buf) {
        if (BLAY == 0) {
#pragma unroll
            for (int i = 0; i < 4; i++)
                *(uint4*)&sh[B_OFFW(buf) + (sr + 64*i) * ASTR + sq*4] =
                    make_uint4(f2tf32(rb[i].x), f2tf32(rb[i].y), f2tf32(rb[i].z), f2tf32(rb[i].w));
        } else {
#pragma unroll
            for (int i = 0; i < 4; i++)
                *(uint4*)&sh[B_OFFW(buf) + (vk + 4*i) * BSTR + vn*4] =
                    make_uint4(f2tf32(rb[i].x), f2tf32(rb[i].y), f2tf32(rb[i].z), f2tf32(rb[i].w));
        }
    };

    ldA(0); ldB(0);
    stA(0); stB(0);
    __syncthreads();

    const int niter = K / BK;
    for (int it = 0; it < niter; it++) {
        const int cb = it & 1, nb = cb ^ 1;
        if (it + 1 < niter) { ldA((it+1)*BK); ldB((it+1)*BK); }

        const uint32_t* As = &sh[A_OFFW(cb)];
        const uint32_t* Bs = &sh[B_OFFW(cb)];
#pragma unroll
        for (int kk = 0; kk < BK; kk += 8) {
            uint32_t af[4][4], bf[8][2];
#pragma unroll
            for (int mt = 0; mt < 4; mt++) {
                const int row = wm + mt*16 + g;
                af[mt][0] = As[row*ASTR + kk + tig];
                af[mt][1] = As[(row+8)*ASTR + kk + tig];
                af[mt][2] = As[row*ASTR + kk + tig + 4];
                af[mt][3] = As[(row+8)*ASTR + kk + tig + 4];
            }
#pragma unroll
            for (int nt = 0; nt < 8; nt++) {
                const int n = wn + nt*8 + g;
                if (BLAY == 0) {
                    bf[nt][0] = Bs[n*ASTR + kk + tig];
                    bf[nt][1] = Bs[n*ASTR + kk + tig + 4];
                } else {
                    bf[nt][0] = Bs[(kk + tig)*BSTR + n];
                    bf[nt][1] = Bs[(kk + tig + 4)*BSTR + n];
                }
            }
#pragma unroll
            for (int mt = 0; mt < 4; mt++)
#pragma unroll
                for (int nt = 0; nt < 8; nt++)
                    mma_tf32(acc[mt][nt], af[mt], bf[nt]);
        }

        if (it + 1 < niter) { stA(nb); stB(nb); }
        __syncthreads();
    }

    // epilogue: c0:(row,col) c1:(row,col+1) c2:(row+8,col) c3:(row+8,col+1)
#pragma unroll
    for (int nt = 0; nt < 8; nt++) {
        const int col = n0 + wn + nt*8 + tig*2;
        float b0 = 0.f, b1 = 0.f;
        if (BIAS) { b0 = bias[col]; b1 = bias[col+1]; }
#pragma unroll
        for (int mt = 0; mt < 4; mt++) {
            const int row = wm + mt*16 + g;
            float v0 = acc[mt][nt][0], v1 = acc[mt][nt][1];
            float v2 = acc[mt][nt][2], v3 = acc[mt][nt][3];
            if (SCALE) { v0 *= alpha; v1 *= alpha; v2 *= alpha; v3 *= alpha; }
            if (BIAS)  { v0 += b0; v1 += b1; v2 += b0; v3 += b1; }
            *(float2*)(C + (size_t)row * ldc + col)     = make_float2(v0, v1);
            *(float2*)(C + (size_t)(row+8) * ldc + col) = make_float2(v2, v3);
        }
    }
}

// ---------------------------------------------------------------------------
__global__ __launch_bounds__(256, 1)
void k_qkv(const float* __restrict__ f4h, const float* __restrict__ f1d,
           const float* __restrict__ f1w,
           const float* __restrict__ Wq, const float* __restrict__ bq,
           const float* __restrict__ Wk, const float* __restrict__ bk,
           const float* __restrict__ Wv, const float* __restrict__ bv)
{
    const int mt = blockIdx.y;
    const int bt = mt >> 3;
    const int b = bt / NT, t = bt - b * NT;
    const float* f = (t == 0) ? f4h : (t == 1) ? f1d : f1w;
    const float* A = f + ((size_t)b * NS + (size_t)(mt & 7) * BM) * ND;

    const float* W; const float* bias; float* Cbuf;
    if (blockIdx.z == 0)      { W = Wq; bias = bq; Cbuf = g_Q; }
    else if (blockIdx.z == 1) { W = Wk; bias = bk; Cbuf = g_K; }
    else                      { W = Wv; bias = bv; Cbuf = g_V; }

    float* C = Cbuf + (size_t)mt * BM * ND;
    gemm_tf32<0, true, false>(A, ND, W, ND, bias, 1.f, C, ND, ND, blockIdx.x * BN);
}

__global__ __launch_bounds__(256, 1)
void k_scores()
{
    const int mt = blockIdx.y;
    const int bt = mt >> 3;
    const float* A  = g_Q + (size_t)mt * BM * ND;
    const float* Bp = g_K + (size_t)bt * NS * ND;
    float* C = g_Sc + (size_t)mt * BM * NS;
    gemm_tf32<0, false, true>(A, ND, Bp, ND, nullptr, 0.044194173824159216f,
                              C, NS, ND, blockIdx.x * BN);
}

__global__ __launch_bounds__(256, 1)
void k_pv()
{
    const int mt = blockIdx.y;
    const int bt = mt >> 3;
    const float* A  = g_Sc + (size_t)mt * BM * NS;   // probs
    const float* Bp = g_V + (size_t)bt * NS * ND;    // V [K x N], N contig
    float* C = g_Q + (size_t)mt * BM * ND;
    gemm_tf32<1, false, false>(A, NS, Bp, ND, nullptr, 1.f, C, ND, NS, blockIdx.x * BN);
}

__global__ __launch_bounds__(256)
void k_softmax()
{
    const int row  = blockIdx.x * 8 + (threadIdx.x >> 5);
    const int lane = threadIdx.x & 31;
    float4* p = (float4*)(g_Sc + (size_t)row * NS);

    float4 v[8];
    float m = -1e30f;
#pragma unroll
    for (int i = 0; i < 8; i++) {
        v[i] = p[lane + 32 * i];
        m = fmaxf(m, fmaxf(fmaxf(v[i].x, v[i].y), fmaxf(v[i].z, v[i].w)));
    }
#pragma unroll
    for (int off = 16; off >= 1; off >>= 1)
        m = fmaxf(m, __shfl_xor_sync(0xffffffffu, m, off));

    float s = 0.f;
#pragma unroll
    for (int i = 0; i < 8; i++) {
        v[i].x = __expf(v[i].x - m); v[i].y = __expf(v[i].y - m);
        v[i].z = __expf(v[i].z - m); v[i].w = __expf(v[i].w - m);
        s += v[i].x + v[i].y + v[i].z + v[i].w;
    }
#pragma unroll
    for (int off = 16; off >= 1; off >>= 1)
        s += __shfl_xor_sync(0xffffffffu, s, off);

    const float inv = 1.0f / s;
#pragma unroll
    for (int i = 0; i < 8; i++) {
        v[i].x *= inv; v[i].y *= inv; v[i].z *= inv; v[i].w *= inv;
        p[lane + 32 * i] = v[i];
    }
}

__global__ __launch_bounds__(256)
void k_combine(const float* __restrict__ tfw, float* __restrict__ out)
{
    float w0 = tfw[0], w1 = tfw[1], w2 = tfw[2];
    float mx = fmaxf(w0, fmaxf(w1, w2));
    float e0 = __expf(w0 - mx), e1 = __expf(w1 - mx), e2 = __expf(w2 - mx);
    float inv = 1.0f / (e0 + e1 + e2);
    w0 = e0 * inv; w1 = e1 * inv; w2 = e2 * inv;

    const size_t per_b = (size_t)NS * ND / 4;
    size_t idx = (size_t)blockIdx.x * blockDim.x + threadIdx.x;
    const size_t n4 = (size_t)NB * per_b;
    if (idx >= n4) return;
    size_t b = idx / per_b;
    size_t r = idx % per_b;

    const float4* A = (const float4*)g_Q;
    float4 x0 = A[(b * 3 + 0) * per_b + r];
    float4 x1 = A[(b * 3 + 1) * per_b + r];
    float4 x2 = A[(b * 3 + 2) * per_b + r];
    float4 o;
    o.x = w0 * x0.x + w1 * x1.x + w2 * x2.x;
    o.y = w0 * x0.y + w1 * x1.y + w2 * x2.y;
    o.z = w0 * x0.z + w1 * x1.z + w2 * x2.z;
    o.w = w0 * x0.w + w1 * x1.w + w2 * x2.w;
    ((float4*)out)[idx] = o;
}

// ---------------------------------------------------------------------------
extern "C" void kernel_launch(void* const* d_in, const int* in_sizes, int n_in,
                              void* d_out, int out_size)
{
    (void)in_sizes; (void)n_in; (void)out_size;
    const float* f4h = (const float*)d_in[0];
    const float* f1d = (const float*)d_in[1];
    const float* f1w = (const float*)d_in[2];
    const float* Wq  = (const float*)d_in[3];
    const float* bq  = (const float*)d_in[4];
    const float* Wk  = (const float*)d_in[5];
    const float* bk  = (const float*)d_in[6];
    const float* Wv  = (const float*)d_in[7];
    const float* bv  = (const float*)d_in[8];
    const float* tfw = (const float*)d_in[9];
    float* out = (float*)d_out;

    const int smem_bytes = SMEM_WORDS * 4;   // 61440
    cudaFuncSetAttribute(k_qkv,    cudaFuncAttributeMaxDynamicSharedMemorySize, smem_bytes);
    cudaFuncSetAttribute(k_scores, cudaFuncAttributeMaxDynamicSharedMemorySize, smem_bytes);
    cudaFuncSetAttribute(k_pv,     cudaFuncAttributeMaxDynamicSharedMemorySize, smem_bytes);

    dim3 blk(256);
    k_qkv    <<<dim3(ND/BN, (NBT*NS)/BM, 3), blk, smem_bytes>>>(f4h, f1d, f1w,
                                                                Wq, bq, Wk, bk, Wv, bv);
    k_scores <<<dim3(NS/BN, (NBT*NS)/BM),    blk, smem_bytes>>>();
    k_softmax<<<(NBT*NS)/8,                  blk>>>();
    k_pv     <<<dim3(ND/BN, (NBT*NS)/BM),    blk, smem_bytes>>>();
    k_combine<<<(NB*NS*ND/4 + 255)/256,      blk>>>(tfw, out);
}

// round 7
// speedup vs baseline: 3.0000x; 1.1920x over previous
#include <cuda_runtime.h>
#include <math.h>
#include <stdint.h>

#define NB   16
#define NS   1024
#define ND   512
#define NT   3
#define NBT  48

__device__ float g_Q [(size_t)NBT * NS * ND];   // Q (tf32 vals); reused as attended
__device__ float g_K [(size_t)NBT * NS * ND];   // K (tf32 vals)
__device__ float g_V [(size_t)NBT * NS * ND];   // V (tf32 vals)
__device__ float g_Sc[(size_t)NBT * NS * NS];   // scores / probs(tf32 vals)
__device__ float g_F [(size_t)NT * NB * NS * ND];  // rounded features
__device__ float g_W [(size_t)NT * ND * ND];       // rounded Wq,Wk,Wv

// ---------------------------------------------------------------------------
// tf32 warp-MMA GEMM v3: CTA tile 128(M) x 256(N), BK=32, 256 threads,
// 8 warps (2x4), warp tile 64x64, cp.async 2-stage pipeline.
// Operands in GMEM are ALREADY tf32-rounded -> raw-bit cp.async is lossless.
// BLAY=0: B is [N x K] row-major (K contig)  -> C = A * B^T
// BLAY=1: B is [K x N] row-major (N contig)  -> C = A * B
// ---------------------------------------------------------------------------
#define ASTR 36         // A/B(K-major) row stride words: 36g+tig mod32 = 4g+tig
#define BSTR 264        // B(N-major) row stride words: 8*tig+g conflict-free
#define A_WORDS 4608    // 128*36
#define B_WORDS 9216    // 256*36 (>= 32*264=8448)
#define STAGE   13824   // A_WORDS + B_WORDS
#define SMEM_WORDS (2*STAGE)   // 27648 words = 110592 B

constexpr int BM = 128, BN = 256, BK = 32;

__device__ __forceinline__ uint32_t f2tf32(float x) {
    uint32_t r; asm("cvt.rna.tf32.f32 %0, %1;" : "=r"(r) : "f"(x)); return r;
}
__device__ __forceinline__ float rna(float x) { return __uint_as_float(f2tf32(x)); }

__device__ __forceinline__ uint32_t smem_u32(const void* p) {
    uint32_t a;
    asm("{ .reg .u64 t; cvta.to.shared.u64 t, %1; cvt.u32.u64 %0, t; }" : "=r"(a) : "l"(p));
    return a;
}
__device__ __forceinline__ void cp16(uint32_t saddr, const void* g) {
    asm volatile("cp.async.cg.shared.global [%0], [%1], 16;" :: "r"(saddr), "l"(g));
}
__device__ __forceinline__ void mma_tf32(float c[4], const uint32_t a[4], const uint32_t b[2]) {
    asm volatile(
        "mma.sync.aligned.m16n8k8.row.col.f32.tf32.tf32.f32 "
        "{%0,%1,%2,%3}, {%4,%5,%6,%7}, {%8,%9}, {%0,%1,%2,%3};"
        : "+f"(c[0]), "+f"(c[1]), "+f"(c[2]), "+f"(c[3])
        : "r"(a[0]), "r"(a[1]), "r"(a[2]), "r"(a[3]), "r"(b[0]), "r"(b[1]));
}

template<int BLAY, bool BIAS, bool SCALE, bool ROUND>
__device__ __forceinline__ void gemm_tf32(
    const float* __restrict__ A, int lda,
    const float* __restrict__ Bm, int ldb,
    const float* __restrict__ bias, float alpha,
    float* __restrict__ C, int ldc, int K, int n0)
{
    extern __shared__ uint32_t sh[];
    const uint32_t sbase = smem_u32(sh);

    const int tid  = threadIdx.x;
    const int lane = tid & 31;
    const int wid  = tid >> 5;
    const int g    = lane >> 2;
    const int tig  = lane & 3;
    const int wm   = (wid & 1) * 64;
    const int wn   = (wid >> 1) * 64;

    float acc[4][8][4];
#pragma unroll
    for (int i = 0; i < 4; i++)
#pragma unroll
        for (int j = 0; j < 8; j++)
#pragma unroll
            for (int q = 0; q < 4; q++) acc[i][j][q] = 0.f;

    // cp.async issue: A = 128 rows x 8 chunks(16B); B = 2048 chunks
    auto issue = [&](int buf, int k0) {
        const uint32_t a0 = sbase + (uint32_t)(buf * STAGE) * 4u;
        const uint32_t b0 = a0 + (uint32_t)A_WORDS * 4u;
#pragma unroll
        for (int i = 0; i < 4; i++) {              // A: 1024 chunks
            const int c = tid + 256 * i, row = c >> 3, q = c & 7;
            cp16(a0 + (uint32_t)(row * ASTR + q * 4) * 4u,
                 A + (size_t)row * lda + k0 + q * 4);
        }
        if (BLAY == 0) {
#pragma unroll
            for (int i = 0; i < 8; i++) {          // B: 256 rows x 8 chunks
                const int c = tid + 256 * i, row = c >> 3, q = c & 7;
                cp16(b0 + (uint32_t)(row * ASTR + q * 4) * 4u,
                     Bm + (size_t)(n0 + row) * ldb + k0 + q * 4);
            }
        } else {
#pragma unroll
            for (int i = 0; i < 8; i++) {          // B: 32 rows x 64 chunks
                const int c = tid + 256 * i, row = c >> 6, q = c & 63;
                cp16(b0 + (uint32_t)(row * BSTR + q * 4) * 4u,
                     Bm + (size_t)(k0 + row) * ldb + n0 + q * 4);
            }
        }
        asm volatile("cp.async.commit_group;" ::: "memory");
    };

    issue(0, 0);
    const int niter = K / BK;
    for (int it = 0; it < niter; it++) {
        if (it + 1 < niter) {
            issue((it + 1) & 1, (it + 1) * BK);
            asm volatile("cp.async.wait_group 1;" ::: "memory");
        } else {
            asm volatile("cp.async.wait_group 0;" ::: "memory");
        }
        __syncthreads();

        const uint32_t* As = &sh[(it & 1) * STAGE];
        const uint32_t* Bs = As + A_WORDS;
#pragma unroll
        for (int kk = 0; kk < BK; kk += 8) {
            uint32_t af[4][4], bf[8][2];
#pragma unroll
            for (int mt = 0; mt < 4; mt++) {
                const int row = wm + mt * 16 + g;
                af[mt][0] = As[row * ASTR + kk + tig];
                af[mt][1] = As[(row + 8) * ASTR + kk + tig];
                af[mt][2] = As[row * ASTR + kk + tig + 4];
                af[mt][3] = As[(row + 8) * ASTR + kk + tig + 4];
            }
#pragma unroll
            for (int nt = 0; nt < 8; nt++) {
                const int n = wn + nt * 8 + g;
                if (BLAY == 0) {
                    bf[nt][0] = Bs[n * ASTR + kk + tig];
                    bf[nt][1] = Bs[n * ASTR + kk + tig + 4];
                } else {
                    bf[nt][0] = Bs[(kk + tig) * BSTR + n];
                    bf[nt][1] = Bs[(kk + tig + 4) * BSTR + n];
                }
            }
#pragma unroll
            for (int mt = 0; mt < 4; mt++)
#pragma unroll
                for (int nt = 0; nt < 8; nt++)
                    mma_tf32(acc[mt][nt], af[mt], bf[nt]);
        }
        __syncthreads();   // compute done before next issue overwrites this buf
    }

    // epilogue
#pragma unroll
    for (int nt = 0; nt < 8; nt++) {
        const int col = n0 + wn + nt * 8 + tig * 2;
        float b0 = 0.f, b1 = 0.f;
        if (BIAS) { b0 = bias[col]; b1 = bias[col + 1]; }
#pragma unroll
        for (int mt = 0; mt < 4; mt++) {
            const int row = wm + mt * 16 + g;
            float v0 = acc[mt][nt][0], v1 = acc[mt][nt][1];
            float v2 = acc[mt][nt][2], v3 = acc[mt][nt][3];
            if (SCALE) { v0 *= alpha; v1 *= alpha; v2 *= alpha; v3 *= alpha; }
            if (BIAS)  { v0 += b0; v1 += b1; v2 += b0; v3 += b1; }
            if (ROUND) { v0 = rna(v0); v1 = rna(v1); v2 = rna(v2); v3 = rna(v3); }
            *(float2*)(C + (size_t)row * ldc + col)       = make_float2(v0, v1);
            *(float2*)(C + (size_t)(row + 8) * ldc + col) = make_float2(v2, v3);
        }
    }
}

// ---------------------------------------------------------------------------
// pre-pass: RNA-round tensors into g_F / g_W
// which 0..2 -> g_F slot; 3..5 -> g_W slot
// ---------------------------------------------------------------------------
__global__ __launch_bounds__(256)
void k_round(const float4* __restrict__ src, int which, int n4)
{
    int idx = blockIdx.x * 256 + threadIdx.x;
    if (idx >= n4) return;
    float4* dst = (which < 3)
        ? (float4*)(g_F + (size_t)which * (NB * NS * ND))
        : (float4*)(g_W + (size_t)(which - 3) * (ND * ND));
    float4 v = src[idx];
    v.x = rna(v.x); v.y = rna(v.y); v.z = rna(v.z); v.w = rna(v.w);
    dst[idx] = v;
}

// ---------------------------------------------------------------------------
__global__ __launch_bounds__(256, 1)
void k_qkv(const float* __restrict__ bq, const float* __restrict__ bk,
           const float* __restrict__ bv)
{
    const int mt = blockIdx.y;
    const int bt = mt >> 3;
    const int b = bt / NT, t = bt - b * NT;
    const float* A = g_F + (size_t)t * (NB * NS * ND)
                         + ((size_t)b * NS + (size_t)(mt & 7) * BM) * ND;
    const float* W = g_W + (size_t)blockIdx.z * (ND * ND);

    const float* bias; float* Cbuf;
    if (blockIdx.z == 0)      { bias = bq; Cbuf = g_Q; }
    else if (blockIdx.z == 1) { bias = bk; Cbuf = g_K; }
    else                      { bias = bv; Cbuf = g_V; }

    float* C = Cbuf + (size_t)mt * BM * ND;
    gemm_tf32<0, true, false, true>(A, ND, W, ND, bias, 1.f, C, ND, ND,
                                    blockIdx.x * BN);
}

__global__ __launch_bounds__(256, 1)
void k_scores()
{
    const int mt = blockIdx.y;
    const int bt = mt >> 3;
    const float* A  = g_Q + (size_t)mt * BM * ND;
    const float* Bp = g_K + (size_t)bt * NS * ND;
    float* C = g_Sc + (size_t)mt * BM * NS;
    gemm_tf32<0, false, true, false>(A, ND, Bp, ND, nullptr,
                                     0.044194173824159216f, C, NS, ND,
                                     blockIdx.x * BN);
}

__global__ __launch_bounds__(256, 1)
void k_pv()
{
    const int mt = blockIdx.y;
    const int bt = mt >> 3;
    const float* A  = g_Sc + (size_t)mt * BM * NS;   // probs (tf32 vals)
    const float* Bp = g_V + (size_t)bt * NS * ND;    // V [K x N] (tf32 vals)
    float* C = g_Q + (size_t)mt * BM * ND;
    gemm_tf32<1, false, false, false>(A, NS, Bp, ND, nullptr, 1.f, C, ND, NS,
                                      blockIdx.x * BN);
}

// ---------------------------------------------------------------------------
__global__ __launch_bounds__(256)
void k_softmax()
{
    const int row  = blockIdx.x * 8 + (threadIdx.x >> 5);
    const int lane = threadIdx.x & 31;
    float4* p = (float4*)(g_Sc + (size_t)row * NS);

    float4 v[8];
    float m = -1e30f;
#pragma unroll
    for (int i = 0; i < 8; i++) {
        v[i] = p[lane + 32 * i];
        m = fmaxf(m, fmaxf(fmaxf(v[i].x, v[i].y), fmaxf(v[i].z, v[i].w)));
    }
#pragma unroll
    for (int off = 16; off >= 1; off >>= 1)
        m = fmaxf(m, __shfl_xor_sync(0xffffffffu, m, off));

    float s = 0.f;
#pragma unroll
    for (int i = 0; i < 8; i++) {
        v[i].x = __expf(v[i].x - m); v[i].y = __expf(v[i].y - m);
        v[i].z = __expf(v[i].z - m); v[i].w = __expf(v[i].w - m);
        s += v[i].x + v[i].y + v[i].z + v[i].w;
    }
#pragma unroll
    for (int off = 16; off >= 1; off >>= 1)
        s += __shfl_xor_sync(0xffffffffu, s, off);

    const float inv = 1.0f / s;
#pragma unroll
    for (int i = 0; i < 8; i++) {
        v[i].x = rna(v[i].x * inv); v[i].y = rna(v[i].y * inv);
        v[i].z = rna(v[i].z * inv); v[i].w = rna(v[i].w * inv);
        p[lane + 32 * i] = v[i];
    }
}

__global__ __launch_bounds__(256)
void k_combine(const float* __restrict__ tfw, float* __restrict__ out)
{
    float w0 = tfw[0], w1 = tfw[1], w2 = tfw[2];
    float mx = fmaxf(w0, fmaxf(w1, w2));
    float e0 = __expf(w0 - mx), e1 = __expf(w1 - mx), e2 = __expf(w2 - mx);
    float inv = 1.0f / (e0 + e1 + e2);
    w0 = e0 * inv; w1 = e1 * inv; w2 = e2 * inv;

    const size_t per_b = (size_t)NS * ND / 4;
    size_t idx = (size_t)blockIdx.x * blockDim.x + threadIdx.x;
    const size_t n4 = (size_t)NB * per_b;
    if (idx >= n4) return;
    size_t b = idx / per_b;
    size_t r = idx % per_b;

    const float4* A = (const float4*)g_Q;
    float4 x0 = A[(b * 3 + 0) * per_b + r];
    float4 x1 = A[(b * 3 + 1) * per_b + r];
    float4 x2 = A[(b * 3 + 2) * per_b + r];
    float4 o;
    o.x = w0 * x0.x + w1 * x1.x + w2 * x2.x;
    o.y = w0 * x0.y + w1 * x1.y + w2 * x2.y;
    o.z = w0 * x0.z + w1 * x1.z + w2 * x2.z;
    o.w = w0 * x0.w + w1 * x1.w + w2 * x2.w;
    ((float4*)out)[idx] = o;
}

// ---------------------------------------------------------------------------
extern "C" void kernel_launch(void* const* d_in, const int* in_sizes, int n_in,
                              void* d_out, int out_size)
{
    (void)in_sizes; (void)n_in; (void)out_size;
    const float* f4h = (const float*)d_in[0];
    const float* f1d = (const float*)d_in[1];
    const float* f1w = (const float*)d_in[2];
    const float* Wq  = (const float*)d_in[3];
    const float* bq  = (const float*)d_in[4];
    const float* Wk  = (const float*)d_in[5];
    const float* bk  = (const float*)d_in[6];
    const float* Wv  = (const float*)d_in[7];
    const float* bv  = (const float*)d_in[8];
    const float* tfw = (const float*)d_in[9];
    float* out = (float*)d_out;

    const int smem_bytes = SMEM_WORDS * 4;   // 110592
    cudaFuncSetAttribute(k_qkv,    cudaFuncAttributeMaxDynamicSharedMemorySize, smem_bytes);
    cudaFuncSetAttribute(k_scores, cudaFuncAttributeMaxDynamicSharedMemorySize, smem_bytes);
    cudaFuncSetAttribute(k_pv,     cudaFuncAttributeMaxDynamicSharedMemorySize, smem_bytes);

    const int nf4 = NB * NS * ND / 4;    // 2,097,152
    const int nw4 = ND * ND / 4;         // 65,536

    dim3 blk(256);
    k_round<<<nf4 / 256, blk>>>((const float4*)f4h, 0, nf4);
    k_round<<<nf4 / 256, blk>>>((const float4*)f1d, 1, nf4);
    k_round<<<nf4 / 256, blk>>>((const float4*)f1w, 2, nf4);
    k_round<<<nw4 / 256, blk>>>((const float4*)Wq, 3, nw4);
    k_round<<<nw4 / 256, blk>>>((const float4*)Wk, 4, nw4);
    k_round<<<nw4 / 256, blk>>>((const float4*)Wv, 5, nw4);

    k_qkv    <<<dim3(ND/BN, (NBT*NS)/BM, 3), blk, smem_bytes>>>(bq, bk, bv);
    k_scores <<<dim3(NS/BN, (NBT*NS)/BM),    blk, smem_bytes>>>();
    k_softmax<<<(NBT*NS)/8,                  blk>>>();
    k_pv     <<<dim3(ND/BN, (NBT*NS)/BM),    blk, smem_bytes>>>();
    k_combine<<<(NB*NS*ND/4 + 255)/256,      blk>>>(tfw, out);
}